// round 1
// baseline (speedup 1.0000x reference)
#include <cuda_runtime.h>

// Problem constants (shapes fixed by the dataset; sizes re-derived at launch).
#define MAX_NODES 100000
#define DIM 64

typedef unsigned long long ull;

// Scratch: precomputed x @ W1[0:64] + b1, and per-node edge counts.
__device__ float g_xw[(size_t)MAX_NODES * DIM];
__device__ float g_cnt[MAX_NODES];

__device__ __forceinline__ void fma2(ull &d, ull a, ull b) {
    asm("fma.rn.f32x2 %0, %1, %2, %0;" : "+l"(d) : "l"(a), "l"(b));
}
__device__ __forceinline__ ull pack2(float lo, float hi) {
    ull r;
    unsigned il = __float_as_uint(lo), ih = __float_as_uint(hi);
    asm("mov.b64 %0, {%1, %2};" : "=l"(r) : "r"(il), "r"(ih));
    return r;
}
__device__ __forceinline__ void unpack2(float &lo, float &hi, ull v) {
    unsigned il, ih;
    asm("mov.b64 {%0, %1}, %2;" : "=r"(il), "=r"(ih) : "l"(v));
    lo = __uint_as_float(il);
    hi = __uint_as_float(ih);
}

// ---------------------------------------------------------------------------
// Kernel 0: zero node-sum region of d_out and the count array.
// ---------------------------------------------------------------------------
__global__ void zero_kernel(float4 *out_node4, int n_nodes) {
    int i = blockIdx.x * blockDim.x + threadIdx.x;
    int total4 = n_nodes * (DIM / 4);
    if (i < total4) out_node4[i] = make_float4(0.f, 0.f, 0.f, 0.f);
    if (i < n_nodes) g_cnt[i] = 0.f;
}

// ---------------------------------------------------------------------------
// Kernel 1: g_xw[n][:] = x[n][:] @ W1[0:64][:] + b1   (per-node precompute)
// One thread per node; inputs staged in S[k][tid]; 32 f32x2 accumulators.
// ---------------------------------------------------------------------------
__global__ __launch_bounds__(256, 2)
void node_pre_kernel(const float *__restrict__ x,
                     const float *__restrict__ W1,
                     const float *__restrict__ b1,
                     int n_nodes) {
    extern __shared__ float smem[];
    float *S   = smem;               // 64 * 256 floats
    float *w1s = S + 64 * 256;       // 64 * 64 floats (W1 rows 0..63)
    float *b1s = w1s + 64 * 64;      // 64 floats

    int tid = threadIdx.x;
    for (int i = tid; i < 64 * 64; i += 256) w1s[i] = W1[i];
    if (tid < 64) b1s[tid] = b1[tid];
    __syncthreads();

    long n = (long)blockIdx.x * 256 + tid;
    bool valid = n < n_nodes;
    long nc = valid ? n : (n_nodes - 1);

    const float4 *xr = (const float4 *)(x + nc * DIM);
#pragma unroll
    for (int q = 0; q < 16; q++) {
        float4 v = xr[q];
        S[(4 * q + 0) * 256 + tid] = v.x;
        S[(4 * q + 1) * 256 + tid] = v.y;
        S[(4 * q + 2) * 256 + tid] = v.z;
        S[(4 * q + 3) * 256 + tid] = v.w;
    }

    ull acc[32];
#pragma unroll
    for (int q = 0; q < 32; q++) acc[q] = pack2(b1s[2 * q], b1s[2 * q + 1]);

    const ulonglong2 *wp = (const ulonglong2 *)w1s;
#pragma unroll 2
    for (int k = 0; k < 64; k++) {
        float av = S[k * 256 + tid];
        ull aa = pack2(av, av);
#pragma unroll
        for (int q = 0; q < 16; q++) {
            ulonglong2 w = wp[k * 16 + q];
            fma2(acc[2 * q], aa, w.x);
            fma2(acc[2 * q + 1], aa, w.y);
        }
    }

    if (valid) {
        float4 *o = (float4 *)(g_xw + n * DIM);
#pragma unroll
        for (int q = 0; q < 16; q++) {
            float a, b, c, d;
            unpack2(a, b, acc[2 * q]);
            unpack2(c, d, acc[2 * q + 1]);
            o[q] = make_float4(a, b, c, d);
        }
    }
}

// ---------------------------------------------------------------------------
// Kernel 2: per-edge MLP + scatter.
//   acc = g_xw[row] (gather)  + edge_attr[e] @ W1[64:128]   -> relu -> h
//   edge_new = h @ W2 + b2
//   out_edge[e] = edge_new;  red.v4 add into out_node[col]; count++
// One thread per edge. No __syncthreads after the weight load: each thread
// owns its private smem column of S, reused for ea then h.
// ---------------------------------------------------------------------------
__global__ __launch_bounds__(256, 2)
void edge_kernel(const float *__restrict__ edge_attr,
                 const float *__restrict__ W1,
                 const float *__restrict__ W2,
                 const float *__restrict__ b2,
                 const int *__restrict__ edge_index,
                 float *__restrict__ out_node,
                 float *__restrict__ out_edge,
                 int n_edges) {
    extern __shared__ float smem[];
    float *S   = smem;               // 64 * 256 floats (ea tile, then h tile)
    float *w1s = S + 64 * 256;       // W1 rows 64..127
    float *w2s = w1s + 64 * 64;      // W2
    float *b2s = w2s + 64 * 64;      // 64 floats

    int tid = threadIdx.x;
    for (int i = tid; i < 64 * 64; i += 256) {
        w1s[i] = W1[64 * 64 + i];
        w2s[i] = W2[i];
    }
    if (tid < 64) b2s[tid] = b2[tid];
    __syncthreads();

    long e = (long)blockIdx.x * 256 + tid;
    bool valid = e < n_edges;
    long ec = valid ? e : (n_edges - 1);
    int row = edge_index[ec];
    int col = edge_index[n_edges + ec];

    // Stage edge_attr row into private smem column (k-indexed).
    const float4 *ea4 = (const float4 *)(edge_attr + ec * DIM);
#pragma unroll
    for (int q = 0; q < 16; q++) {
        float4 v = ea4[q];
        S[(4 * q + 0) * 256 + tid] = v.x;
        S[(4 * q + 1) * 256 + tid] = v.y;
        S[(4 * q + 2) * 256 + tid] = v.z;
        S[(4 * q + 3) * 256 + tid] = v.w;
    }

    // Accumulator init = gathered xw row (L2-resident table, b1 folded in).
    ull acc[32];
    const float4 *xw4 = (const float4 *)(g_xw + (long)row * DIM);
#pragma unroll
    for (int q = 0; q < 16; q++) {
        float4 v = xw4[q];
        acc[2 * q]     = pack2(v.x, v.y);
        acc[2 * q + 1] = pack2(v.z, v.w);
    }

    // GEMM1: acc += ea @ W1b
    {
        const ulonglong2 *wp = (const ulonglong2 *)w1s;
#pragma unroll 2
        for (int k = 0; k < 64; k++) {
            float av = S[k * 256 + tid];
            ull aa = pack2(av, av);
#pragma unroll
            for (int q = 0; q < 16; q++) {
                ulonglong2 w = wp[k * 16 + q];
                fma2(acc[2 * q], aa, w.x);
                fma2(acc[2 * q + 1], aa, w.y);
            }
        }
    }

    // relu -> stage h into the same smem column; re-init acc with b2.
#pragma unroll
    for (int q = 0; q < 32; q++) {
        float lo, hi;
        unpack2(lo, hi, acc[q]);
        lo = fmaxf(lo, 0.f);
        hi = fmaxf(hi, 0.f);
        S[(2 * q) * 256 + tid]     = lo;
        S[(2 * q + 1) * 256 + tid] = hi;
        acc[q] = pack2(b2s[2 * q], b2s[2 * q + 1]);
    }

    // GEMM2: acc = h @ W2 + b2
    {
        const ulonglong2 *wp = (const ulonglong2 *)w2s;
#pragma unroll 2
        for (int k = 0; k < 64; k++) {
            float av = S[k * 256 + tid];
            ull aa = pack2(av, av);
#pragma unroll
            for (int q = 0; q < 16; q++) {
                ulonglong2 w = wp[k * 16 + q];
                fma2(acc[2 * q], aa, w.x);
                fma2(acc[2 * q + 1], aa, w.y);
            }
        }
    }

    if (valid) {
        float4 *oe = (float4 *)(out_edge + e * DIM);
        float *on = out_node + (long)col * DIM;
#pragma unroll
        for (int q = 0; q < 16; q++) {
            float a, b, c, d;
            unpack2(a, b, acc[2 * q]);
            unpack2(c, d, acc[2 * q + 1]);
            oe[q] = make_float4(a, b, c, d);
            asm volatile("red.global.add.v4.f32 [%0], {%1,%2,%3,%4};"
                         :: "l"(on + 4 * q), "f"(a), "f"(b), "f"(c), "f"(d)
                         : "memory");
        }
        atomicAdd(&g_cnt[col], 1.0f);
    }
}

// ---------------------------------------------------------------------------
// Kernel 3: node_new = node_sum / max(cnt, 1)
// ---------------------------------------------------------------------------
__global__ void finalize_kernel(float4 *out_node4, int n_nodes) {
    int i = blockIdx.x * blockDim.x + threadIdx.x;
    int total4 = n_nodes * (DIM / 4);
    if (i >= total4) return;
    int n = i >> 4;                      // 16 float4 per node row
    float c = fmaxf(g_cnt[n], 1.0f);
    float inv = 1.0f / c;
    float4 v = out_node4[i];
    v.x *= inv; v.y *= inv; v.z *= inv; v.w *= inv;
    out_node4[i] = v;
}

// ---------------------------------------------------------------------------
extern "C" void kernel_launch(void* const* d_in, const int* in_sizes, int n_in,
                              void* d_out, int out_size) {
    const float *x    = (const float *)d_in[0];
    const float *ea   = (const float *)d_in[1];
    const float *W1   = (const float *)d_in[2];
    const float *b1   = (const float *)d_in[3];
    const float *W2   = (const float *)d_in[4];
    const float *b2   = (const float *)d_in[5];
    const int   *eidx = (const int *)d_in[6];

    int n_nodes = in_sizes[0] / DIM;
    int n_edges = in_sizes[1] / DIM;

    float *out_node = (float *)d_out;
    float *out_edge = out_node + (size_t)n_nodes * DIM;

    const int smem_pre  = (64 * 256 + 64 * 64 + 64) * 4;
    const int smem_edge = (64 * 256 + 2 * 64 * 64 + 64) * 4;
    cudaFuncSetAttribute(node_pre_kernel,
                         cudaFuncAttributeMaxDynamicSharedMemorySize, smem_pre);
    cudaFuncSetAttribute(edge_kernel,
                         cudaFuncAttributeMaxDynamicSharedMemorySize, smem_edge);

    int z_grid = (n_nodes * (DIM / 4) + 255) / 256;
    zero_kernel<<<z_grid, 256>>>((float4 *)out_node, n_nodes);

    int pre_grid = (n_nodes + 255) / 256;
    node_pre_kernel<<<pre_grid, 256, smem_pre>>>(x, W1, b1, n_nodes);

    int e_grid = (n_edges + 255) / 256;
    edge_kernel<<<e_grid, 256, smem_edge>>>(ea, W1, W2, b2, eidx,
                                            out_node, out_edge, n_edges);

    finalize_kernel<<<z_grid, 256>>>((float4 *)out_node, n_nodes);
}

// round 3
// speedup vs baseline: 1.8673x; 1.8673x over previous
#include <cuda_runtime.h>
#include <cuda_bf16.h>
#include <cstdint>

#define MAX_NODES 100000
#define DIM 64

typedef unsigned long long ull;

// Scratch: precomputed x @ W1[0:64] + b1, and per-node edge counts.
__device__ float g_xw[(size_t)MAX_NODES * DIM];
__device__ float g_cnt[MAX_NODES];

// ---------------------------------------------------------------------------
// helpers
// ---------------------------------------------------------------------------
__device__ __forceinline__ uint32_t smem_u32(const void *p) {
    uint32_t a;
    asm("{ .reg .u64 t; cvta.to.shared.u64 t, %1; cvt.u32.u64 %0, t; }"
        : "=r"(a) : "l"(p));
    return a;
}
__device__ __forceinline__ uint32_t swz(uint32_t o) { return o ^ ((o >> 3) & 0x70); }

__device__ __forceinline__ void ldsm4(uint32_t &r0, uint32_t &r1, uint32_t &r2,
                                      uint32_t &r3, uint32_t a) {
    asm volatile("ldmatrix.sync.aligned.m8n8.x4.shared.b16 {%0,%1,%2,%3}, [%4];"
                 : "=r"(r0), "=r"(r1), "=r"(r2), "=r"(r3) : "r"(a));
}
__device__ __forceinline__ void mma16816(float *d, uint32_t a0, uint32_t a1,
                                         uint32_t a2, uint32_t a3,
                                         uint32_t b0, uint32_t b1) {
    asm volatile(
        "mma.sync.aligned.m16n8k16.row.col.f32.bf16.bf16.f32 "
        "{%0,%1,%2,%3}, {%4,%5,%6,%7}, {%8,%9}, {%0,%1,%2,%3};"
        : "+f"(d[0]), "+f"(d[1]), "+f"(d[2]), "+f"(d[3])
        : "r"(a0), "r"(a1), "r"(a2), "r"(a3), "r"(b0), "r"(b1));
}
// pack (lo=f0, hi=f1) as bf16x2
__device__ __forceinline__ uint32_t pack_bf2(float f0, float f1) {
    uint32_t r;
    asm("cvt.rn.bf16x2.f32 %0, %1, %2;" : "=r"(r) : "f"(f1), "f"(f0));
    return r;
}
// split pair into hi bf16x2 and lo bf16x2 (a = hi + lo)
__device__ __forceinline__ void split_pair(float f0, float f1, uint32_t &h, uint32_t &l) {
    h = pack_bf2(f0, f1);
    float h0 = __uint_as_float(h << 16);
    float h1 = __uint_as_float(h & 0xFFFF0000u);
    l = pack_bf2(f0 - h0, f1 - h1);
}
__device__ __forceinline__ void red_v4(float *p, float4 v) {
    asm volatile("red.global.add.v4.f32 [%0], {%1,%2,%3,%4};"
                 :: "l"(p), "f"(v.x), "f"(v.y), "f"(v.z), "f"(v.w) : "memory");
}
// fp32x2 helpers (node precompute)
__device__ __forceinline__ void fma2(ull &d, ull a, ull b) {
    asm("fma.rn.f32x2 %0, %1, %2, %0;" : "+l"(d) : "l"(a), "l"(b));
}
__device__ __forceinline__ ull pack2(float lo, float hi) {
    ull r; unsigned il = __float_as_uint(lo), ih = __float_as_uint(hi);
    asm("mov.b64 %0, {%1, %2};" : "=l"(r) : "r"(il), "r"(ih));
    return r;
}
__device__ __forceinline__ void unpack2(float &lo, float &hi, ull v) {
    unsigned il, ih;
    asm("mov.b64 {%0, %1}, %2;" : "=r"(il), "=r"(ih) : "l"(v));
    lo = __uint_as_float(il); hi = __uint_as_float(ih);
}

// ---------------------------------------------------------------------------
// Kernel 0: zero node-sum region and counts
// ---------------------------------------------------------------------------
__global__ void zero_kernel(float4 *out_node4, int n_nodes) {
    int i = blockIdx.x * blockDim.x + threadIdx.x;
    int total4 = n_nodes * (DIM / 4);
    if (i < total4) out_node4[i] = make_float4(0.f, 0.f, 0.f, 0.f);
    if (i < n_nodes) g_cnt[i] = 0.f;
}

// ---------------------------------------------------------------------------
// Kernel 1: g_xw = x @ W1[0:64] + b1 (scalar fp32x2)
// ---------------------------------------------------------------------------
__global__ __launch_bounds__(256, 2)
void node_pre_kernel(const float *__restrict__ x, const float *__restrict__ W1,
                     const float *__restrict__ b1, int n_nodes) {
    extern __shared__ float smem[];
    float *S = smem, *w1s = S + 64 * 256, *b1s = w1s + 64 * 64;
    int tid = threadIdx.x;
    for (int i = tid; i < 64 * 64; i += 256) w1s[i] = W1[i];
    if (tid < 64) b1s[tid] = b1[tid];
    __syncthreads();

    long n = (long)blockIdx.x * 256 + tid;
    bool valid = n < n_nodes;
    long nc = valid ? n : (n_nodes - 1);
    const float4 *xr = (const float4 *)(x + nc * DIM);
#pragma unroll
    for (int q = 0; q < 16; q++) {
        float4 v = xr[q];
        S[(4 * q + 0) * 256 + tid] = v.x; S[(4 * q + 1) * 256 + tid] = v.y;
        S[(4 * q + 2) * 256 + tid] = v.z; S[(4 * q + 3) * 256 + tid] = v.w;
    }
    ull acc[32];
#pragma unroll
    for (int q = 0; q < 32; q++) acc[q] = pack2(b1s[2 * q], b1s[2 * q + 1]);
    const ulonglong2 *wp = (const ulonglong2 *)w1s;
#pragma unroll 2
    for (int k = 0; k < 64; k++) {
        float av = S[k * 256 + tid];
        ull aa = pack2(av, av);
#pragma unroll
        for (int q = 0; q < 16; q++) {
            ulonglong2 w = wp[k * 16 + q];
            fma2(acc[2 * q], aa, w.x);
            fma2(acc[2 * q + 1], aa, w.y);
        }
    }
    if (valid) {
        float4 *o = (float4 *)(g_xw + n * DIM);
#pragma unroll
        for (int q = 0; q < 16; q++) {
            float a, b, c, d;
            unpack2(a, b, acc[2 * q]); unpack2(c, d, acc[2 * q + 1]);
            o[q] = make_float4(a, b, c, d);
        }
    }
}

// ---------------------------------------------------------------------------
// Kernel 2: mma.sync edge MLP + scatter.
// Warp-autonomous: each warp owns a 16-edge tile; no CTA syncs in mainloop.
// SMEM (64KB/CTA):
//   [0,8K)   W1H  (W1 rows 64..127 as [n][k] bf16-hi, SW128 rows of 128B)
//   [8K,16K) W1L
//   [16K,24K)W2H
//   [24K,32K)W2L
//   [32K+w*4K, +2K)  per-warp A/h hi tile (16x64 bf16)
//   [.. +2K, +4K)    per-warp A/h lo tile   (also reused as 4KB fp32 scratch)
// ---------------------------------------------------------------------------
struct Frag { uint32_t x, y, z, w; };

__device__ __forceinline__ void gemm_3pass(uint32_t aH, uint32_t aL,
                                           uint32_t wH, uint32_t wL,
                                           float d[8][4], int lane) {
    uint32_t a_row = (lane & 7) + ((lane >> 3) & 1) * 8;
    uint32_t a_kq  = (lane >> 4) * 16;
    uint32_t b_row = (lane & 7) + ((lane >> 4) & 1) * 8;
    uint32_t b_kq  = ((lane >> 3) & 1) * 16;
#pragma unroll
    for (int ks = 0; ks < 4; ks++) {
        uint32_t aoff = swz(a_row * 128 + ks * 32 + a_kq);
        Frag ah, al;
        ldsm4(ah.x, ah.y, ah.z, ah.w, aH + aoff);
        ldsm4(al.x, al.y, al.z, al.w, aL + aoff);
#pragma unroll
        for (int p = 0; p < 4; p++) {
            uint32_t boff = swz((b_row + p * 16) * 128 + ks * 32 + b_kq);
            Frag bh, bl;
            ldsm4(bh.x, bh.y, bh.z, bh.w, wH + boff);
            ldsm4(bl.x, bl.y, bl.z, bl.w, wL + boff);
            mma16816(d[2 * p],     ah.x, ah.y, ah.z, ah.w, bh.x, bh.y);
            mma16816(d[2 * p + 1], ah.x, ah.y, ah.z, ah.w, bh.z, bh.w);
            mma16816(d[2 * p],     ah.x, ah.y, ah.z, ah.w, bl.x, bl.y);
            mma16816(d[2 * p + 1], ah.x, ah.y, ah.z, ah.w, bl.z, bl.w);
            mma16816(d[2 * p],     al.x, al.y, al.z, al.w, bh.x, bh.y);
            mma16816(d[2 * p + 1], al.x, al.y, al.z, al.w, bh.z, bh.w);
        }
    }
}

__global__ __launch_bounds__(256, 2)
void edge_kernel(const float *__restrict__ edge_attr,
                 const float *__restrict__ W1,
                 const float *__restrict__ W2,
                 const float *__restrict__ b2,
                 const int *__restrict__ edge_index,
                 float *__restrict__ out_node,
                 float *__restrict__ out_edge,
                 int n_edges, int n_wtiles) {
    extern __shared__ char smc[];
    uint32_t sb = smem_u32(smc);
    int tid = threadIdx.x;
    int wid = tid >> 5, lane = tid & 31;

    // ---- stage split-bf16 weights, [n][k] rows of 128B, swizzled ----
    for (int i = tid; i < 4096; i += 256) {
        int kk = i >> 6, n = i & 63;
        uint32_t off = swz((uint32_t)(n * 128 + kk * 2));
        float wv1 = W1[(64 + kk) * 64 + n];
        float wv2 = W2[kk * 64 + n];
        __nv_bfloat16 h1 = __float2bfloat16(wv1);
        __nv_bfloat16 l1 = __float2bfloat16(wv1 - __bfloat162float(h1));
        __nv_bfloat16 h2 = __float2bfloat16(wv2);
        __nv_bfloat16 l2 = __float2bfloat16(wv2 - __bfloat162float(h2));
        *(uint16_t *)(smc + 0     + off) = __bfloat16_as_ushort(h1);
        *(uint16_t *)(smc + 8192  + off) = __bfloat16_as_ushort(l1);
        *(uint16_t *)(smc + 16384 + off) = __bfloat16_as_ushort(h2);
        *(uint16_t *)(smc + 24576 + off) = __bfloat16_as_ushort(l2);
    }
    __syncthreads();

    const uint32_t W1H = sb, W1L = sb + 8192, W2H = sb + 16384, W2L = sb + 24576;
    char *wbuf = smc + 32768 + wid * 4096;        // per-warp tile buffer
    const uint32_t AH = sb + 32768 + wid * 4096;
    const uint32_t AL = AH + 2048;

    // per-thread b2 fragment columns: n = j*8 + 2*(lane&3)
    int cb = 2 * (lane & 3);
    float b2r[16];
#pragma unroll
    for (int j = 0; j < 8; j++) {
        float2 v = *(const float2 *)(b2 + j * 8 + cb);
        b2r[2 * j] = v.x; b2r[2 * j + 1] = v.y;
    }

    int q = lane >> 2;                  // D-frag row group (0..7)
    int nwarps = gridDim.x * 8;
    int wgid = blockIdx.x * 8 + wid;

    for (int wt = wgid; wt < n_wtiles; wt += nwarps) {
        int base_e = wt * 16;

        // ---- stage 16x64 edge_attr tile as split bf16 ----
#pragma unroll
        for (int j = 0; j < 8; j++) {
            int idx = j * 32 + lane;
            int m = idx >> 4, c = idx & 15;
            int e = base_e + m; if (e >= n_edges) e = n_edges - 1;
            float4 v = *(const float4 *)(edge_attr + (long)e * 64 + c * 4);
            uint32_t h01, l01, h23, l23;
            split_pair(v.x, v.y, h01, l01);
            split_pair(v.z, v.w, h23, l23);
            uint32_t off = swz((uint32_t)(m * 128 + c * 8));
            *(uint2 *)(wbuf + off)        = make_uint2(h01, h23);
            *(uint2 *)(wbuf + 2048 + off) = make_uint2(l01, l23);
        }
        __syncwarp();

        // ---- GEMM1: D1 = ea @ W1b (3-pass split) ----
        float d1[8][4];
#pragma unroll
        for (int j = 0; j < 8; j++)
            d1[j][0] = d1[j][1] = d1[j][2] = d1[j][3] = 0.f;
        gemm_3pass(AH, AL, W1H, W1L, d1, lane);

        // ---- epilogue 1: h = relu(D1 + xw[src]); write h tile ----
        int e0 = base_e + q;     if (e0 >= n_edges) e0 = n_edges - 1;
        int e1 = base_e + q + 8; if (e1 >= n_edges) e1 = n_edges - 1;
        int s0 = edge_index[e0], s1 = edge_index[e1];
        const float *xw0 = g_xw + (long)s0 * 64;
        const float *xw1 = g_xw + (long)s1 * 64;
#pragma unroll
        for (int j = 0; j < 8; j++) {
            float2 x0 = *(const float2 *)(xw0 + j * 8 + cb);
            float2 x1 = *(const float2 *)(xw1 + j * 8 + cb);
            float h00 = fmaxf(d1[j][0] + x0.x, 0.f);
            float h01 = fmaxf(d1[j][1] + x0.y, 0.f);
            float h10 = fmaxf(d1[j][2] + x1.x, 0.f);
            float h11 = fmaxf(d1[j][3] + x1.y, 0.f);
            uint32_t h, l;
            uint32_t off0 = swz((uint32_t)(q * 128 + (j * 8 + cb) * 2));
            uint32_t off1 = swz((uint32_t)((q + 8) * 128 + (j * 8 + cb) * 2));
            split_pair(h00, h01, h, l);
            *(uint32_t *)(wbuf + off0) = h;
            *(uint32_t *)(wbuf + 2048 + off0) = l;
            split_pair(h10, h11, h, l);
            *(uint32_t *)(wbuf + off1) = h;
            *(uint32_t *)(wbuf + 2048 + off1) = l;
        }
        __syncwarp();

        // ---- GEMM2: D2 = h @ W2 (3-pass split) ----
        float d2[8][4];
#pragma unroll
        for (int j = 0; j < 8; j++)
            d2[j][0] = d2[j][1] = d2[j][2] = d2[j][3] = 0.f;
        gemm_3pass(AH, AL, W2H, W2L, d2, lane);

        // ---- epilogue 2: + b2, smem transpose, coalesced store + scatter ----
        float *sc = (float *)wbuf;      // 4KB fp32 scratch [16][64]
        __syncwarp();                   // GEMM2 ldmatrix done before overwrite
#pragma unroll
        for (int j = 0; j < 8; j++) {
            *(float2 *)(sc + q * 64 + j * 8 + cb) =
                make_float2(d2[j][0] + b2r[2 * j], d2[j][1] + b2r[2 * j + 1]);
            *(float2 *)(sc + (q + 8) * 64 + j * 8 + cb) =
                make_float2(d2[j][2] + b2r[2 * j], d2[j][3] + b2r[2 * j + 1]);
        }
        __syncwarp();
        {
            int row = lane >> 1, hf = lane & 1;
            int er = base_e + row;
            bool valid = er < n_edges;
            int erc = valid ? er : (n_edges - 1);
            int dst = edge_index[n_edges + erc];
            const float4 *s4 = (const float4 *)(sc + row * 64 + hf * 32);
            if (valid) {
                float4 *oe = (float4 *)(out_edge + (long)er * 64 + hf * 32);
                float *on = out_node + (long)dst * 64 + hf * 32;
#pragma unroll
                for (int t = 0; t < 8; t++) {
                    float4 v = s4[t];
                    oe[t] = v;
                    red_v4(on + 4 * t, v);
                }
                if (hf == 0)
                    asm volatile("red.global.add.f32 [%0], %1;"
                                 :: "l"(g_cnt + dst), "f"(1.0f) : "memory");
            }
        }
        __syncwarp();                   // scratch free before next staging
    }
}

// ---------------------------------------------------------------------------
// Kernel 3: node_new = node_sum / max(cnt, 1)
// ---------------------------------------------------------------------------
__global__ void finalize_kernel(float4 *out_node4, int n_nodes) {
    int i = blockIdx.x * blockDim.x + threadIdx.x;
    int total4 = n_nodes * (DIM / 4);
    if (i >= total4) return;
    int n = i >> 4;
    float inv = 1.0f / fmaxf(g_cnt[n], 1.0f);
    float4 v = out_node4[i];
    v.x *= inv; v.y *= inv; v.z *= inv; v.w *= inv;
    out_node4[i] = v;
}

// ---------------------------------------------------------------------------
extern "C" void kernel_launch(void* const* d_in, const int* in_sizes, int n_in,
                              void* d_out, int out_size) {
    const float *x    = (const float *)d_in[0];
    const float *ea   = (const float *)d_in[1];
    const float *W1   = (const float *)d_in[2];
    const float *b1   = (const float *)d_in[3];
    const float *W2   = (const float *)d_in[4];
    const float *b2   = (const float *)d_in[5];
    const int   *eidx = (const int *)d_in[6];

    int n_nodes = in_sizes[0] / DIM;
    int n_edges = in_sizes[1] / DIM;

    float *out_node = (float *)d_out;
    float *out_edge = out_node + (size_t)n_nodes * DIM;

    const int smem_pre  = (64 * 256 + 64 * 64 + 64) * 4;
    const int smem_edge = 65536;
    cudaFuncSetAttribute(node_pre_kernel,
                         cudaFuncAttributeMaxDynamicSharedMemorySize, smem_pre);
    cudaFuncSetAttribute(edge_kernel,
                         cudaFuncAttributeMaxDynamicSharedMemorySize, smem_edge);

    int z_grid = (n_nodes * (DIM / 4) + 255) / 256;
    zero_kernel<<<z_grid, 256>>>((float4 *)out_node, n_nodes);

    int pre_grid = (n_nodes + 255) / 256;
    node_pre_kernel<<<pre_grid, 256, smem_pre>>>(x, W1, b1, n_nodes);

    int n_wtiles = (n_edges + 15) / 16;
    int grid = 296;
    int max_grid = (n_wtiles + 7) / 8;
    if (grid > max_grid) grid = max_grid;
    edge_kernel<<<grid, 256, smem_edge>>>(ea, W1, W2, b2, eidx,
                                          out_node, out_edge, n_edges, n_wtiles);

    finalize_kernel<<<z_grid, 256>>>((float4 *)out_node, n_nodes);
}

// round 5
// speedup vs baseline: 2.0104x; 1.0766x over previous
#include <cuda_runtime.h>
#include <cuda_bf16.h>
#include <cstdint>

#define MAX_NODES 100000
#define DIM 64

typedef unsigned long long ull;

// Scratch: precomputed x @ W1[0:64] + b1, and per-node edge counts.
__device__ float g_xw[(size_t)MAX_NODES * DIM];
__device__ float g_cnt[MAX_NODES];

// ---------------------------------------------------------------------------
// helpers
// ---------------------------------------------------------------------------
__device__ __forceinline__ uint32_t smem_u32(const void *p) {
    uint32_t a;
    asm("{ .reg .u64 t; cvta.to.shared.u64 t, %1; cvt.u32.u64 %0, t; }"
        : "=r"(a) : "l"(p));
    return a;
}
__device__ __forceinline__ uint32_t swz(uint32_t o) { return o ^ ((o >> 3) & 0x70); }

__device__ __forceinline__ void ldsm4(uint32_t &r0, uint32_t &r1, uint32_t &r2,
                                      uint32_t &r3, uint32_t a) {
    asm volatile("ldmatrix.sync.aligned.m8n8.x4.shared.b16 {%0,%1,%2,%3}, [%4];"
                 : "=r"(r0), "=r"(r1), "=r"(r2), "=r"(r3) : "r"(a));
}
__device__ __forceinline__ void mma16816(float *d, uint32_t a0, uint32_t a1,
                                         uint32_t a2, uint32_t a3,
                                         uint32_t b0, uint32_t b1) {
    asm volatile(
        "mma.sync.aligned.m16n8k16.row.col.f32.bf16.bf16.f32 "
        "{%0,%1,%2,%3}, {%4,%5,%6,%7}, {%8,%9}, {%0,%1,%2,%3};"
        : "+f"(d[0]), "+f"(d[1]), "+f"(d[2]), "+f"(d[3])
        : "r"(a0), "r"(a1), "r"(a2), "r"(a3), "r"(b0), "r"(b1));
}
__device__ __forceinline__ uint32_t pack_bf2(float f0, float f1) {
    uint32_t r;
    asm("cvt.rn.bf16x2.f32 %0, %1, %2;" : "=r"(r) : "f"(f1), "f"(f0));
    return r;
}
__device__ __forceinline__ void split_pair(float f0, float f1, uint32_t &h, uint32_t &l) {
    h = pack_bf2(f0, f1);
    float h0 = __uint_as_float(h << 16);
    float h1 = __uint_as_float(h & 0xFFFF0000u);
    l = pack_bf2(f0 - h0, f1 - h1);
}
__device__ __forceinline__ void red_v4(float *p, float4 v) {
    asm volatile("red.global.add.v4.f32 [%0], {%1,%2,%3,%4};"
                 :: "l"(p), "f"(v.x), "f"(v.y), "f"(v.z), "f"(v.w) : "memory");
}
__device__ __forceinline__ void cp16(uint32_t dst, const void *src) {
    asm volatile("cp.async.cg.shared.global [%0], [%1], 16;"
                 :: "r"(dst), "l"(src) : "memory");
}
// fp32x2 helpers (node precompute)
__device__ __forceinline__ void fma2(ull &d, ull a, ull b) {
    asm("fma.rn.f32x2 %0, %1, %2, %0;" : "+l"(d) : "l"(a), "l"(b));
}
__device__ __forceinline__ ull pack2(float lo, float hi) {
    ull r; unsigned il = __float_as_uint(lo), ih = __float_as_uint(hi);
    asm("mov.b64 %0, {%1, %2};" : "=l"(r) : "r"(il), "r"(ih));
    return r;
}
__device__ __forceinline__ void unpack2(float &lo, float &hi, ull v) {
    unsigned il, ih;
    asm("mov.b64 {%0, %1}, %2;" : "=r"(il), "=r"(ih) : "l"(v));
    lo = __uint_as_float(il); hi = __uint_as_float(ih);
}

// ---------------------------------------------------------------------------
// Kernel 0: zero node-sum region and counts
// ---------------------------------------------------------------------------
__global__ void zero_kernel(float4 *out_node4, int n_nodes) {
    int i = blockIdx.x * blockDim.x + threadIdx.x;
    int total4 = n_nodes * (DIM / 4);
    if (i < total4) out_node4[i] = make_float4(0.f, 0.f, 0.f, 0.f);
    if (i < n_nodes) g_cnt[i] = 0.f;
}

// ---------------------------------------------------------------------------
// Kernel 1: g_xw = x @ W1[0:64] + b1 (scalar fp32x2)
// ---------------------------------------------------------------------------
__global__ __launch_bounds__(256, 2)
void node_pre_kernel(const float *__restrict__ x, const float *__restrict__ W1,
                     const float *__restrict__ b1, int n_nodes) {
    extern __shared__ float smem[];
    float *S = smem, *w1s = S + 64 * 256, *b1s = w1s + 64 * 64;
    int tid = threadIdx.x;
    for (int i = tid; i < 64 * 64; i += 256) w1s[i] = W1[i];
    if (tid < 64) b1s[tid] = b1[tid];
    __syncthreads();

    long n = (long)blockIdx.x * 256 + tid;
    bool valid = n < n_nodes;
    long nc = valid ? n : (n_nodes - 1);
    const float4 *xr = (const float4 *)(x + nc * DIM);
#pragma unroll
    for (int q = 0; q < 16; q++) {
        float4 v = xr[q];
        S[(4 * q + 0) * 256 + tid] = v.x; S[(4 * q + 1) * 256 + tid] = v.y;
        S[(4 * q + 2) * 256 + tid] = v.z; S[(4 * q + 3) * 256 + tid] = v.w;
    }
    ull acc[32];
#pragma unroll
    for (int q = 0; q < 32; q++) acc[q] = pack2(b1s[2 * q], b1s[2 * q + 1]);
    const ulonglong2 *wp = (const ulonglong2 *)w1s;
#pragma unroll 2
    for (int k = 0; k < 64; k++) {
        float av = S[k * 256 + tid];
        ull aa = pack2(av, av);
#pragma unroll
        for (int q = 0; q < 16; q++) {
            ulonglong2 w = wp[k * 16 + q];
            fma2(acc[2 * q], aa, w.x);
            fma2(acc[2 * q + 1], aa, w.y);
        }
    }
    if (valid) {
        float4 *o = (float4 *)(g_xw + n * DIM);
#pragma unroll
        for (int q = 0; q < 16; q++) {
            float a, b, c, d;
            unpack2(a, b, acc[2 * q]); unpack2(c, d, acc[2 * q + 1]);
            o[q] = make_float4(a, b, c, d);
        }
    }
}

// ---------------------------------------------------------------------------
// Kernel 2: mma.sync edge MLP + scatter, pipelined.
// Per-warp 16-edge tiles; cp.async prefetch of xw gather; ea tile double-
// buffered in registers. SMEM per CTA:
//   [0,32K)        W1H/W1L/W2H/W2L (8K each, [n][k] SW128 rows of 128B)
//   32K + wid*8704 : AH(2K) AL(2K) XW(16 rows x 272B = 4352, padded)
//   102400         : b2 (256B)
// ---------------------------------------------------------------------------
#define WBUF_STRIDE 8704
#define SM_B2 (32768 + 8 * WBUF_STRIDE)
#define SM_TOTAL (SM_B2 + 256)
#define XW_PITCH 272

struct Frag { uint32_t x, y, z, w; };

__device__ __forceinline__ void gemm_3pass(uint32_t aH, uint32_t aL,
                                           uint32_t wH, uint32_t wL,
                                           float d[8][4], int lane) {
    uint32_t a_row = (lane & 7) + ((lane >> 3) & 1) * 8;
    uint32_t a_kq  = (lane >> 4) * 16;
    uint32_t b_row = (lane & 7) + ((lane >> 4) & 1) * 8;
    uint32_t b_kq  = ((lane >> 3) & 1) * 16;
#pragma unroll
    for (int ks = 0; ks < 4; ks++) {
        uint32_t aoff = swz(a_row * 128 + ks * 32 + a_kq);
        Frag ah, al;
        ldsm4(ah.x, ah.y, ah.z, ah.w, aH + aoff);
        ldsm4(al.x, al.y, al.z, al.w, aL + aoff);
#pragma unroll
        for (int p = 0; p < 4; p++) {
            uint32_t boff = swz((b_row + p * 16) * 128 + ks * 32 + b_kq);
            Frag bh, bl;
            ldsm4(bh.x, bh.y, bh.z, bh.w, wH + boff);
            ldsm4(bl.x, bl.y, bl.z, bl.w, wL + boff);
            mma16816(d[2 * p],     ah.x, ah.y, ah.z, ah.w, bh.x, bh.y);
            mma16816(d[2 * p + 1], ah.x, ah.y, ah.z, ah.w, bh.z, bh.w);
            mma16816(d[2 * p],     ah.x, ah.y, ah.z, ah.w, bl.x, bl.y);
            mma16816(d[2 * p + 1], ah.x, ah.y, ah.z, ah.w, bl.z, bl.w);
            mma16816(d[2 * p],     al.x, al.y, al.z, al.w, bh.x, bh.y);
            mma16816(d[2 * p + 1], al.x, al.y, al.z, al.w, bh.z, bh.w);
        }
    }
}

__global__ __launch_bounds__(256, 2)
void edge_kernel(const float *__restrict__ edge_attr,
                 const float *__restrict__ W1,
                 const float *__restrict__ W2,
                 const float *__restrict__ b2,
                 const int *__restrict__ edge_index,
                 float *__restrict__ out_node,
                 float *__restrict__ out_edge,
                 int n_edges, int n_wtiles) {
    extern __shared__ char smc[];
    uint32_t sb = smem_u32(smc);
    int tid = threadIdx.x;
    int wid = tid >> 5, lane = tid & 31;

    // ---- stage split-bf16 weights ----
    for (int i = tid; i < 4096; i += 256) {
        int kk = i >> 6, n = i & 63;
        uint32_t off = swz((uint32_t)(n * 128 + kk * 2));
        float wv1 = W1[(64 + kk) * 64 + n];
        float wv2 = W2[kk * 64 + n];
        __nv_bfloat16 h1 = __float2bfloat16(wv1);
        __nv_bfloat16 l1 = __float2bfloat16(wv1 - __bfloat162float(h1));
        __nv_bfloat16 h2 = __float2bfloat16(wv2);
        __nv_bfloat16 l2 = __float2bfloat16(wv2 - __bfloat162float(h2));
        *(uint16_t *)(smc + 0     + off) = __bfloat16_as_ushort(h1);
        *(uint16_t *)(smc + 8192  + off) = __bfloat16_as_ushort(l1);
        *(uint16_t *)(smc + 16384 + off) = __bfloat16_as_ushort(h2);
        *(uint16_t *)(smc + 24576 + off) = __bfloat16_as_ushort(l2);
    }
    if (tid < 64) ((float *)(smc + SM_B2))[tid] = b2[tid];
    __syncthreads();

    const uint32_t W1H = sb, W1L = sb + 8192, W2H = sb + 16384, W2L = sb + 24576;
    char *wbuf = smc + 32768 + wid * WBUF_STRIDE;    // AH/AL (4KB)
    char *xwbuf = wbuf + 4096;                       // 16 x 272B
    const uint32_t AH = sb + 32768 + wid * WBUF_STRIDE;
    const uint32_t AL = AH + 2048;
    const uint32_t XW = AH + 4096;

    int q = lane >> 2, cb = 2 * (lane & 3);          // D-fragment mapping
    int row2 = lane >> 1, hf = lane & 1;             // gather/store mapping
    int nwarps = gridDim.x * 8;
    int wgid = blockIdx.x * 8 + wid;

    // preload first ea tile into registers
    float4 ea[8];
    if (wgid < n_wtiles) {
        int base = wgid * 16;
#pragma unroll
        for (int j = 0; j < 8; j++) {
            int idx = j * 32 + lane;
            int e = base + (idx >> 4); if (e >= n_edges) e = n_edges - 1;
            ea[j] = *(const float4 *)(edge_attr + (long)e * 64 + (idx & 15) * 4);
        }
    }

    for (int wt = wgid; wt < n_wtiles; wt += nwarps) {
        int base_e = wt * 16;

        // ---- edge indices: lanes 0-15 -> src, 16-31 -> dst ----
        int pos = base_e + (lane & 15);
        if (pos >= n_edges) pos = n_edges - 1;
        int idxv = edge_index[(lane < 16 ? 0 : n_edges) + pos];
        int srcr = __shfl_sync(0xffffffffu, idxv, row2);
        int dstr = __shfl_sync(0xffffffffu, idxv, 16 + row2);

        // ---- cp.async prefetch of xw[src] rows (4KB gather) ----
        {
            const float *g = g_xw + (long)srcr * 64 + hf * 32;
            uint32_t d = XW + row2 * XW_PITCH + hf * 128;
#pragma unroll
            for (int i = 0; i < 8; i++) cp16(d + i * 16, g + i * 4);
            asm volatile("cp.async.commit_group;" ::: "memory");
        }

        // ---- stage ea registers -> split-bf16 A tiles ----
#pragma unroll
        for (int j = 0; j < 8; j++) {
            int idx = j * 32 + lane;
            int m = idx >> 4, c = idx & 15;
            uint32_t h01, l01, h23, l23;
            split_pair(ea[j].x, ea[j].y, h01, l01);
            split_pair(ea[j].z, ea[j].w, h23, l23);
            uint32_t off = swz((uint32_t)(m * 128 + c * 8));
            *(uint2 *)(wbuf + off)        = make_uint2(h01, h23);
            *(uint2 *)(wbuf + 2048 + off) = make_uint2(l01, l23);
        }
        __syncwarp();

        // ---- issue next tile's ea loads (consumed next iteration) ----
        int wtn = wt + nwarps;
        if (wtn < n_wtiles) {
            int base = wtn * 16;
#pragma unroll
            for (int j = 0; j < 8; j++) {
                int idx = j * 32 + lane;
                int e = base + (idx >> 4); if (e >= n_edges) e = n_edges - 1;
                ea[j] = *(const float4 *)(edge_attr + (long)e * 64 + (idx & 15) * 4);
            }
        }

        // ---- GEMM1: D1 = ea @ W1b (3-pass split) ----
        float d1[8][4];
#pragma unroll
        for (int j = 0; j < 8; j++)
            d1[j][0] = d1[j][1] = d1[j][2] = d1[j][3] = 0.f;
        gemm_3pass(AH, AL, W1H, W1L, d1, lane);

        // ---- epilogue 1: h = relu(D1 + xw) from prefetched smem ----
        asm volatile("cp.async.wait_group 0;" ::: "memory");
        __syncwarp();
        const float *xw0 = (const float *)(xwbuf + q * XW_PITCH);
        const float *xw1 = (const float *)(xwbuf + (q + 8) * XW_PITCH);
#pragma unroll
        for (int j = 0; j < 8; j++) {
            float2 x0 = *(const float2 *)(xw0 + j * 8 + cb);
            float2 x1 = *(const float2 *)(xw1 + j * 8 + cb);
            float h00 = fmaxf(d1[j][0] + x0.x, 0.f);
            float h01 = fmaxf(d1[j][1] + x0.y, 0.f);
            float h10 = fmaxf(d1[j][2] + x1.x, 0.f);
            float h11 = fmaxf(d1[j][3] + x1.y, 0.f);
            uint32_t h, l;
            uint32_t off0 = swz((uint32_t)(q * 128 + (j * 8 + cb) * 2));
            uint32_t off1 = swz((uint32_t)((q + 8) * 128 + (j * 8 + cb) * 2));
            split_pair(h00, h01, h, l);
            *(uint32_t *)(wbuf + off0) = h;
            *(uint32_t *)(wbuf + 2048 + off0) = l;
            split_pair(h10, h11, h, l);
            *(uint32_t *)(wbuf + off1) = h;
            *(uint32_t *)(wbuf + 2048 + off1) = l;
        }
        __syncwarp();

        // ---- GEMM2: D2 = h @ W2 (3-pass split) ----
        float d2[8][4];
#pragma unroll
        for (int j = 0; j < 8; j++)
            d2[j][0] = d2[j][1] = d2[j][2] = d2[j][3] = 0.f;
        gemm_3pass(AH, AL, W2H, W2L, d2, lane);

        // ---- epilogue 2: transpose via padded xw buffer, +b2, store+scatter ----
        float *sc = (float *)xwbuf;                  // rows of 68 floats
#pragma unroll
        for (int j = 0; j < 8; j++) {
            *(float2 *)(sc + q * 68 + j * 8 + cb) =
                make_float2(d2[j][0], d2[j][1]);
            *(float2 *)(sc + (q + 8) * 68 + j * 8 + cb) =
                make_float2(d2[j][2], d2[j][3]);
        }
        __syncwarp();
        {
            int er = base_e + row2;
            if (er < n_edges) {
                const float4 *s4 = (const float4 *)(sc + row2 * 68 + hf * 32);
                const float4 *b2v = (const float4 *)(smc + SM_B2 + hf * 128);
                float4 *oe = (float4 *)(out_edge + (long)er * 64 + hf * 32);
                float *on = out_node + (long)dstr * 64 + hf * 32;
#pragma unroll
                for (int t = 0; t < 8; t++) {
                    float4 v = s4[t], b = b2v[t];
                    v.x += b.x; v.y += b.y; v.z += b.z; v.w += b.w;
                    oe[t] = v;
                    red_v4(on + 4 * t, v);
                }
                if (hf == 0)
                    asm volatile("red.global.add.f32 [%0], %1;"
                                 :: "l"(g_cnt + dstr), "f"(1.0f) : "memory");
            }
        }
        __syncwarp();
    }
}

// ---------------------------------------------------------------------------
// Kernel 3: node_new = node_sum / max(cnt, 1)
// ---------------------------------------------------------------------------
__global__ void finalize_kernel(float4 *out_node4, int n_nodes) {
    int i = blockIdx.x * blockDim.x + threadIdx.x;
    int total4 = n_nodes * (DIM / 4);
    if (i >= total4) return;
    int n = i >> 4;
    float inv = 1.0f / fmaxf(g_cnt[n], 1.0f);
    float4 v = out_node4[i];
    v.x *= inv; v.y *= inv; v.z *= inv; v.w *= inv;
    out_node4[i] = v;
}

// ---------------------------------------------------------------------------
extern "C" void kernel_launch(void* const* d_in, const int* in_sizes, int n_in,
                              void* d_out, int out_size) {
    const float *x    = (const float *)d_in[0];
    const float *ea   = (const float *)d_in[1];
    const float *W1   = (const float *)d_in[2];
    const float *b1   = (const float *)d_in[3];
    const float *W2   = (const float *)d_in[4];
    const float *b2   = (const float *)d_in[5];
    const int   *eidx = (const int *)d_in[6];

    int n_nodes = in_sizes[0] / DIM;
    int n_edges = in_sizes[1] / DIM;

    float *out_node = (float *)d_out;
    float *out_edge = out_node + (size_t)n_nodes * DIM;

    const int smem_pre = (64 * 256 + 64 * 64 + 64) * 4;
    cudaFuncSetAttribute(node_pre_kernel,
                         cudaFuncAttributeMaxDynamicSharedMemorySize, smem_pre);
    cudaFuncSetAttribute(edge_kernel,
                         cudaFuncAttributeMaxDynamicSharedMemorySize, SM_TOTAL);

    int z_grid = (n_nodes * (DIM / 4) + 255) / 256;
    zero_kernel<<<z_grid, 256>>>((float4 *)out_node, n_nodes);

    int pre_grid = (n_nodes + 255) / 256;
    node_pre_kernel<<<pre_grid, 256, smem_pre>>>(x, W1, b1, n_nodes);

    int n_wtiles = (n_edges + 15) / 16;
    int grid = 296;
    int max_grid = (n_wtiles + 7) / 8;
    if (grid > max_grid) grid = max_grid;
    edge_kernel<<<grid, 256, SM_TOTAL>>>(ea, W1, W2, b2, eidx,
                                         out_node, out_edge, n_edges, n_wtiles);

    finalize_kernel<<<z_grid, 256>>>((float4 *)out_node, n_nodes);
}

// round 7
// speedup vs baseline: 2.0777x; 1.0335x over previous
#include <cuda_runtime.h>
#include <cuda_fp16.h>
#include <cstdint>

#define MAX_NODES 100000
#define DIM 64

typedef unsigned long long ull;

// Scratch: precomputed x @ W1[0:64] + b1, and per-node edge counts.
__device__ float g_xw[(size_t)MAX_NODES * DIM];
__device__ float g_cnt[MAX_NODES];

// W pre-scale (power of two, exact): keeps wl out of fp16 subnormal range.
#define WSCALE 16.0f
#define INV_WSCALE 0.0625f

// ---------------------------------------------------------------------------
// helpers
// ---------------------------------------------------------------------------
__device__ __forceinline__ uint32_t smem_u32(const void *p) {
    uint32_t a;
    asm("{ .reg .u64 t; cvta.to.shared.u64 t, %1; cvt.u32.u64 %0, t; }"
        : "=r"(a) : "l"(p));
    return a;
}
__device__ __forceinline__ uint32_t swz(uint32_t o) { return o ^ ((o >> 3) & 0x70); }

__device__ __forceinline__ void ldsm4(uint32_t &r0, uint32_t &r1, uint32_t &r2,
                                      uint32_t &r3, uint32_t a) {
    asm volatile("ldmatrix.sync.aligned.m8n8.x4.shared.b16 {%0,%1,%2,%3}, [%4];"
                 : "=r"(r0), "=r"(r1), "=r"(r2), "=r"(r3) : "r"(a));
}
__device__ __forceinline__ void mma16816(float *d, uint32_t a0, uint32_t a1,
                                         uint32_t a2, uint32_t a3,
                                         uint32_t b0, uint32_t b1) {
    asm volatile(
        "mma.sync.aligned.m16n8k16.row.col.f32.f16.f16.f32 "
        "{%0,%1,%2,%3}, {%4,%5,%6,%7}, {%8,%9}, {%0,%1,%2,%3};"
        : "+f"(d[0]), "+f"(d[1]), "+f"(d[2]), "+f"(d[3])
        : "r"(a0), "r"(a1), "r"(a2), "r"(a3), "r"(b0), "r"(b1));
}
// pack (lo=f0, hi=f1) as fp16x2
__device__ __forceinline__ uint32_t pack_h2(float f0, float f1) {
    uint32_t r;
    asm("cvt.rn.f16x2.f32 %0, %1, %2;" : "=r"(r) : "f"(f1), "f"(f0));
    return r;
}
__device__ __forceinline__ void red_v4(float *p, float4 v) {
    asm volatile("red.global.add.v4.f32 [%0], {%1,%2,%3,%4};"
                 :: "l"(p), "f"(v.x), "f"(v.y), "f"(v.z), "f"(v.w) : "memory");
}
__device__ __forceinline__ void cp16(uint32_t dst, const void *src) {
    asm volatile("cp.async.cg.shared.global [%0], [%1], 16;"
                 :: "r"(dst), "l"(src) : "memory");
}
// fp32x2 helpers (node precompute)
__device__ __forceinline__ void fma2(ull &d, ull a, ull b) {
    asm("fma.rn.f32x2 %0, %1, %2, %0;" : "+l"(d) : "l"(a), "l"(b));
}
__device__ __forceinline__ ull pack2(float lo, float hi) {
    ull r; unsigned il = __float_as_uint(lo), ih = __float_as_uint(hi);
    asm("mov.b64 %0, {%1, %2};" : "=l"(r) : "r"(il), "r"(ih));
    return r;
}
__device__ __forceinline__ void unpack2(float &lo, float &hi, ull v) {
    unsigned il, ih;
    asm("mov.b64 {%0, %1}, %2;" : "=r"(il), "=r"(ih) : "l"(v));
    lo = __uint_as_float(il); hi = __uint_as_float(ih);
}

// ---------------------------------------------------------------------------
// Kernel 0: zero node-sum region and counts
// ---------------------------------------------------------------------------
__global__ void zero_kernel(float4 *out_node4, int n_nodes) {
    int i = blockIdx.x * blockDim.x + threadIdx.x;
    int total4 = n_nodes * (DIM / 4);
    if (i < total4) out_node4[i] = make_float4(0.f, 0.f, 0.f, 0.f);
    if (i < n_nodes) g_cnt[i] = 0.f;
}

// ---------------------------------------------------------------------------
// Kernel 1: g_xw = x @ W1[0:64] + b1 (scalar fp32x2)
// ---------------------------------------------------------------------------
__global__ __launch_bounds__(256, 2)
void node_pre_kernel(const float *__restrict__ x, const float *__restrict__ W1,
                     const float *__restrict__ b1, int n_nodes) {
    extern __shared__ float smem[];
    float *S = smem, *w1s = S + 64 * 256, *b1s = w1s + 64 * 64;
    int tid = threadIdx.x;
    for (int i = tid; i < 64 * 64; i += 256) w1s[i] = W1[i];
    if (tid < 64) b1s[tid] = b1[tid];
    __syncthreads();

    long n = (long)blockIdx.x * 256 + tid;
    bool valid = n < n_nodes;
    long nc = valid ? n : (n_nodes - 1);
    const float4 *xr = (const float4 *)(x + nc * DIM);
#pragma unroll
    for (int q = 0; q < 16; q++) {
        float4 v = xr[q];
        S[(4 * q + 0) * 256 + tid] = v.x; S[(4 * q + 1) * 256 + tid] = v.y;
        S[(4 * q + 2) * 256 + tid] = v.z; S[(4 * q + 3) * 256 + tid] = v.w;
    }
    ull acc[32];
#pragma unroll
    for (int q = 0; q < 32; q++) acc[q] = pack2(b1s[2 * q], b1s[2 * q + 1]);
    const ulonglong2 *wp = (const ulonglong2 *)w1s;
#pragma unroll 2
    for (int k = 0; k < 64; k++) {
        float av = S[k * 256 + tid];
        ull aa = pack2(av, av);
#pragma unroll
        for (int q = 0; q < 16; q++) {
            ulonglong2 w = wp[k * 16 + q];
            fma2(acc[2 * q], aa, w.x);
            fma2(acc[2 * q + 1], aa, w.y);
        }
    }
    if (valid) {
        float4 *o = (float4 *)(g_xw + n * DIM);
#pragma unroll
        for (int q = 0; q < 16; q++) {
            float a, b, c, d;
            unpack2(a, b, acc[2 * q]); unpack2(c, d, acc[2 * q + 1]);
            o[q] = make_float4(a, b, c, d);
        }
    }
}

// ---------------------------------------------------------------------------
// Kernel 2: mma.sync fp16 2-pass edge MLP + scatter, pipelined.
// A single fp16; W split into (wh, wl) fp16, pre-scaled by 16 (D * 1/16 in
// epilogues). Per-warp 16-edge tiles; cp.async xw prefetch; ea register
// double-buffering. SMEM per CTA:
//   [0,32K)  W1H/W1L/W2H/W2L (8K each, [n][k] rows of 128B, swizzled)
//   32K + wid*6528 : AF(2K) XW(16 x 272B = 4352)
//   84992    : b2 (256B)
// ---------------------------------------------------------------------------
#define WBUF_STRIDE 6528
#define SM_B2 (32768 + 8 * WBUF_STRIDE)
#define SM_TOTAL (SM_B2 + 256)
#define XW_PITCH 272

struct Frag { uint32_t x, y, z, w; };

// D += A(fp16) @ [Wh + Wl]^T, both passes into the same f32 accumulators.
__device__ __forceinline__ void gemm_2pass(uint32_t aF,
                                           uint32_t wH, uint32_t wL,
                                           float d[8][4], int lane) {
    uint32_t a_row = (lane & 7) + ((lane >> 3) & 1) * 8;
    uint32_t a_kq  = (lane >> 4) * 16;
    uint32_t b_row = (lane & 7) + ((lane >> 4) & 1) * 8;
    uint32_t b_kq  = ((lane >> 3) & 1) * 16;
#pragma unroll
    for (int ks = 0; ks < 4; ks++) {
        uint32_t aoff = swz(a_row * 128 + ks * 32 + a_kq);
        Frag af;
        ldsm4(af.x, af.y, af.z, af.w, aF + aoff);
#pragma unroll
        for (int p = 0; p < 4; p++) {
            uint32_t boff = swz((b_row + p * 16) * 128 + ks * 32 + b_kq);
            Frag bh, bl;
            ldsm4(bh.x, bh.y, bh.z, bh.w, wH + boff);
            ldsm4(bl.x, bl.y, bl.z, bl.w, wL + boff);
            mma16816(d[2 * p],     af.x, af.y, af.z, af.w, bh.x, bh.y);
            mma16816(d[2 * p + 1], af.x, af.y, af.z, af.w, bh.z, bh.w);
            mma16816(d[2 * p],     af.x, af.y, af.z, af.w, bl.x, bl.y);
            mma16816(d[2 * p + 1], af.x, af.y, af.z, af.w, bl.z, bl.w);
        }
    }
}

__global__ __launch_bounds__(256, 2)
void edge_kernel(const float *__restrict__ edge_attr,
                 const float *__restrict__ W1,
                 const float *__restrict__ W2,
                 const float *__restrict__ b2,
                 const int *__restrict__ edge_index,
                 float *__restrict__ out_node,
                 float *__restrict__ out_edge,
                 int n_edges, int n_wtiles) {
    extern __shared__ char smc[];
    uint32_t sb = smem_u32(smc);
    int tid = threadIdx.x;
    int wid = tid >> 5, lane = tid & 31;

    // ---- stage split-fp16 weights (scaled by 16) ----
    for (int i = tid; i < 4096; i += 256) {
        int kk = i >> 6, n = i & 63;
        uint32_t off = swz((uint32_t)(n * 128 + kk * 2));
        float wv1 = W1[(64 + kk) * 64 + n] * WSCALE;
        float wv2 = W2[kk * 64 + n] * WSCALE;
        __half h1 = __float2half_rn(wv1);
        __half l1 = __float2half_rn(wv1 - __half2float(h1));
        __half h2 = __float2half_rn(wv2);
        __half l2 = __float2half_rn(wv2 - __half2float(h2));
        *(uint16_t *)(smc + 0     + off) = __half_as_ushort(h1);
        *(uint16_t *)(smc + 8192  + off) = __half_as_ushort(l1);
        *(uint16_t *)(smc + 16384 + off) = __half_as_ushort(h2);
        *(uint16_t *)(smc + 24576 + off) = __half_as_ushort(l2);
    }
    if (tid < 64) ((float *)(smc + SM_B2))[tid] = b2[tid];
    __syncthreads();

    const uint32_t W1H = sb, W1L = sb + 8192, W2H = sb + 16384, W2L = sb + 24576;
    char *wbuf = smc + 32768 + wid * WBUF_STRIDE;    // AF (2KB)
    char *xwbuf = wbuf + 2048;                       // 16 x 272B
    const uint32_t AF = sb + 32768 + wid * WBUF_STRIDE;
    const uint32_t XW = AF + 2048;

    int q = lane >> 2, cb = 2 * (lane & 3);          // D-fragment mapping
    int row2 = lane >> 1, hf = lane & 1;             // gather/store mapping
    int nwarps = gridDim.x * 8;
    int wgid = blockIdx.x * 8 + wid;

    // preload first ea tile into registers
    float4 ea[8];
    if (wgid < n_wtiles) {
        int base = wgid * 16;
#pragma unroll
        for (int j = 0; j < 8; j++) {
            int idx = j * 32 + lane;
            int e = base + (idx >> 4); if (e >= n_edges) e = n_edges - 1;
            ea[j] = *(const float4 *)(edge_attr + (long)e * 64 + (idx & 15) * 4);
        }
    }

    for (int wt = wgid; wt < n_wtiles; wt += nwarps) {
        int base_e = wt * 16;

        // ---- edge indices: lanes 0-15 -> src, 16-31 -> dst ----
        int pos = base_e + (lane & 15);
        if (pos >= n_edges) pos = n_edges - 1;
        int idxv = edge_index[(lane < 16 ? 0 : n_edges) + pos];
        int srcr = __shfl_sync(0xffffffffu, idxv, row2);
        int dstr = __shfl_sync(0xffffffffu, idxv, 16 + row2);

        // ---- cp.async prefetch of xw[src] rows (4KB gather) ----
        {
            const float *g = g_xw + (long)srcr * 64 + hf * 32;
            uint32_t d = XW + row2 * XW_PITCH + hf * 128;
#pragma unroll
            for (int i = 0; i < 8; i++) cp16(d + i * 16, g + i * 4);
            asm volatile("cp.async.commit_group;" ::: "memory");
        }

        // ---- stage ea registers -> fp16 A tile ----
#pragma unroll
        for (int j = 0; j < 8; j++) {
            int idx = j * 32 + lane;
            int m = idx >> 4, c = idx & 15;
            uint32_t h01 = pack_h2(ea[j].x, ea[j].y);
            uint32_t h23 = pack_h2(ea[j].z, ea[j].w);
            uint32_t off = swz((uint32_t)(m * 128 + c * 8));
            *(uint2 *)(wbuf + off) = make_uint2(h01, h23);
        }
        __syncwarp();

        // ---- issue next tile's ea loads (consumed next iteration) ----
        int wtn = wt + nwarps;
        if (wtn < n_wtiles) {
            int base = wtn * 16;
#pragma unroll
            for (int j = 0; j < 8; j++) {
                int idx = j * 32 + lane;
                int e = base + (idx >> 4); if (e >= n_edges) e = n_edges - 1;
                ea[j] = *(const float4 *)(edge_attr + (long)e * 64 + (idx & 15) * 4);
            }
        }

        // ---- GEMM1: D1 = ea @ (W1h + W1l), scaled by 16 ----
        float d1[8][4];
#pragma unroll
        for (int j = 0; j < 8; j++)
            d1[j][0] = d1[j][1] = d1[j][2] = d1[j][3] = 0.f;
        gemm_2pass(AF, W1H, W1L, d1, lane);

        // ---- epilogue 1: h = relu(D1/16 + xw) from prefetched smem ----
        asm volatile("cp.async.wait_group 0;" ::: "memory");
        __syncwarp();
        const float *xw0 = (const float *)(xwbuf + q * XW_PITCH);
        const float *xw1 = (const float *)(xwbuf + (q + 8) * XW_PITCH);
#pragma unroll
        for (int j = 0; j < 8; j++) {
            float2 x0 = *(const float2 *)(xw0 + j * 8 + cb);
            float2 x1 = *(const float2 *)(xw1 + j * 8 + cb);
            float h00 = fmaxf(fmaf(d1[j][0], INV_WSCALE, x0.x), 0.f);
            float h01 = fmaxf(fmaf(d1[j][1], INV_WSCALE, x0.y), 0.f);
            float h10 = fmaxf(fmaf(d1[j][2], INV_WSCALE, x1.x), 0.f);
            float h11 = fmaxf(fmaf(d1[j][3], INV_WSCALE, x1.y), 0.f);
            uint32_t off0 = swz((uint32_t)(q * 128 + (j * 8 + cb) * 2));
            uint32_t off1 = swz((uint32_t)((q + 8) * 128 + (j * 8 + cb) * 2));
            *(uint32_t *)(wbuf + off0) = pack_h2(h00, h01);
            *(uint32_t *)(wbuf + off1) = pack_h2(h10, h11);
        }
        __syncwarp();

        // ---- GEMM2: D2 = h @ (W2h + W2l), scaled by 16 ----
        float d2[8][4];
#pragma unroll
        for (int j = 0; j < 8; j++)
            d2[j][0] = d2[j][1] = d2[j][2] = d2[j][3] = 0.f;
        gemm_2pass(AF, W2H, W2L, d2, lane);

        // ---- epilogue 2: transpose via xw buffer, scale + b2, store+scatter ----
        float *sc = (float *)xwbuf;                  // rows of 68 floats
#pragma unroll
        for (int j = 0; j < 8; j++) {
            *(float2 *)(sc + q * 68 + j * 8 + cb) =
                make_float2(d2[j][0] * INV_WSCALE, d2[j][1] * INV_WSCALE);
            *(float2 *)(sc + (q + 8) * 68 + j * 8 + cb) =
                make_float2(d2[j][2] * INV_WSCALE, d2[j][3] * INV_WSCALE);
        }
        __syncwarp();
        {
            int er = base_e + row2;
            if (er < n_edges) {
                const float4 *s4 = (const float4 *)(sc + row2 * 68 + hf * 32);
                const float4 *b2v = (const float4 *)(smc + SM_B2 + hf * 128);
                float4 *oe = (float4 *)(out_edge + (long)er * 64 + hf * 32);
                float *on = out_node + (long)dstr * 64 + hf * 32;
#pragma unroll
                for (int t = 0; t < 8; t++) {
                    float4 v = s4[t], b = b2v[t];
                    v.x += b.x; v.y += b.y; v.z += b.z; v.w += b.w;
                    oe[t] = v;
                    red_v4(on + 4 * t, v);
                }
                if (hf == 0)
                    asm volatile("red.global.add.f32 [%0], %1;"
                                 :: "l"(g_cnt + dstr), "f"(1.0f) : "memory");
            }
        }
        __syncwarp();
    }
}

// ---------------------------------------------------------------------------
// Kernel 3: node_new = node_sum / max(cnt, 1)
// ---------------------------------------------------------------------------
__global__ void finalize_kernel(float4 *out_node4, int n_nodes) {
    int i = blockIdx.x * blockDim.x + threadIdx.x;
    int total4 = n_nodes * (DIM / 4);
    if (i >= total4) return;
    int n = i >> 4;
    float inv = 1.0f / fmaxf(g_cnt[n], 1.0f);
    float4 v = out_node4[i];
    v.x *= inv; v.y *= inv; v.z *= inv; v.w *= inv;
    out_node4[i] = v;
}

// ---------------------------------------------------------------------------
extern "C" void kernel_launch(void* const* d_in, const int* in_sizes, int n_in,
                              void* d_out, int out_size) {
    const float *x    = (const float *)d_in[0];
    const float *ea   = (const float *)d_in[1];
    const float *W1   = (const float *)d_in[2];
    const float *b1   = (const float *)d_in[3];
    const float *W2   = (const float *)d_in[4];
    const float *b2   = (const float *)d_in[5];
    const int   *eidx = (const int *)d_in[6];

    int n_nodes = in_sizes[0] / DIM;
    int n_edges = in_sizes[1] / DIM;

    float *out_node = (float *)d_out;
    float *out_edge = out_node + (size_t)n_nodes * DIM;

    const int smem_pre = (64 * 256 + 64 * 64 + 64) * 4;
    cudaFuncSetAttribute(node_pre_kernel,
                         cudaFuncAttributeMaxDynamicSharedMemorySize, smem_pre);
    cudaFuncSetAttribute(edge_kernel,
                         cudaFuncAttributeMaxDynamicSharedMemorySize, SM_TOTAL);

    int z_grid = (n_nodes * (DIM / 4) + 255) / 256;
    zero_kernel<<<z_grid, 256>>>((float4 *)out_node, n_nodes);

    int pre_grid = (n_nodes + 255) / 256;
    node_pre_kernel<<<pre_grid, 256, smem_pre>>>(x, W1, b1, n_nodes);

    int n_wtiles = (n_edges + 15) / 16;
    int grid = 296;
    int max_grid = (n_wtiles + 7) / 8;
    if (grid > max_grid) grid = max_grid;
    edge_kernel<<<grid, 256, SM_TOTAL>>>(ea, W1, W2, b2, eidx,
                                         out_node, out_edge, n_edges, n_wtiles);

    finalize_kernel<<<z_grid, 256>>>((float4 *)out_node, n_nodes);
}

// round 8
// speedup vs baseline: 2.2581x; 1.0868x over previous
#include <cuda_runtime.h>
#include <cuda_fp16.h>
#include <cstdint>

#define MAX_NODES 100000
#define DIM 64

typedef unsigned long long ull;

// Scratch: precomputed x @ W1[0:64] + b1, and per-node edge counts.
__device__ float g_xw[(size_t)MAX_NODES * DIM];
__device__ float g_cnt[MAX_NODES];

// ---------------------------------------------------------------------------
// helpers
// ---------------------------------------------------------------------------
__device__ __forceinline__ uint32_t smem_u32(const void *p) {
    uint32_t a;
    asm("{ .reg .u64 t; cvta.to.shared.u64 t, %1; cvt.u32.u64 %0, t; }"
        : "=r"(a) : "l"(p));
    return a;
}
__device__ __forceinline__ uint32_t swz(uint32_t o) { return o ^ ((o >> 3) & 0x70); }

__device__ __forceinline__ void ldsm4(uint32_t &r0, uint32_t &r1, uint32_t &r2,
                                      uint32_t &r3, uint32_t a) {
    asm volatile("ldmatrix.sync.aligned.m8n8.x4.shared.b16 {%0,%1,%2,%3}, [%4];"
                 : "=r"(r0), "=r"(r1), "=r"(r2), "=r"(r3) : "r"(a));
}
__device__ __forceinline__ void mma16816(float *d, uint32_t a0, uint32_t a1,
                                         uint32_t a2, uint32_t a3,
                                         uint32_t b0, uint32_t b1) {
    asm volatile(
        "mma.sync.aligned.m16n8k16.row.col.f32.f16.f16.f32 "
        "{%0,%1,%2,%3}, {%4,%5,%6,%7}, {%8,%9}, {%0,%1,%2,%3};"
        : "+f"(d[0]), "+f"(d[1]), "+f"(d[2]), "+f"(d[3])
        : "r"(a0), "r"(a1), "r"(a2), "r"(a3), "r"(b0), "r"(b1));
}
// pack (lo=f0, hi=f1) as fp16x2
__device__ __forceinline__ uint32_t pack_h2(float f0, float f1) {
    uint32_t r;
    asm("cvt.rn.f16x2.f32 %0, %1, %2;" : "=r"(r) : "f"(f1), "f"(f0));
    return r;
}
__device__ __forceinline__ void red_v4(float *p, float4 v) {
    asm volatile("red.global.add.v4.f32 [%0], {%1,%2,%3,%4};"
                 :: "l"(p), "f"(v.x), "f"(v.y), "f"(v.z), "f"(v.w) : "memory");
}
__device__ __forceinline__ void cp16(uint32_t dst, const void *src) {
    asm volatile("cp.async.cg.shared.global [%0], [%1], 16;"
                 :: "r"(dst), "l"(src) : "memory");
}
// fp32x2 helpers (node precompute)
__device__ __forceinline__ void fma2(ull &d, ull a, ull b) {
    asm("fma.rn.f32x2 %0, %1, %2, %0;" : "+l"(d) : "l"(a), "l"(b));
}
__device__ __forceinline__ ull pack2(float lo, float hi) {
    ull r; unsigned il = __float_as_uint(lo), ih = __float_as_uint(hi);
    asm("mov.b64 %0, {%1, %2};" : "=l"(r) : "r"(il), "r"(ih));
    return r;
}
__device__ __forceinline__ void unpack2(float &lo, float &hi, ull v) {
    unsigned il, ih;
    asm("mov.b64 {%0, %1}, %2;" : "=r"(il), "=r"(ih) : "l"(v));
    lo = __uint_as_float(il); hi = __uint_as_float(ih);
}

// ---------------------------------------------------------------------------
// Kernel 0: zero node-sum region and counts
// ---------------------------------------------------------------------------
__global__ void zero_kernel(float4 *out_node4, int n_nodes) {
    int i = blockIdx.x * blockDim.x + threadIdx.x;
    int total4 = n_nodes * (DIM / 4);
    if (i < total4) out_node4[i] = make_float4(0.f, 0.f, 0.f, 0.f);
    if (i < n_nodes) g_cnt[i] = 0.f;
}

// ---------------------------------------------------------------------------
// Kernel 1: g_xw = x @ W1[0:64] + b1 (scalar fp32x2)
// ---------------------------------------------------------------------------
__global__ __launch_bounds__(256, 2)
void node_pre_kernel(const float *__restrict__ x, const float *__restrict__ W1,
                     const float *__restrict__ b1, int n_nodes) {
    extern __shared__ float smem[];
    float *S = smem, *w1s = S + 64 * 256, *b1s = w1s + 64 * 64;
    int tid = threadIdx.x;
    for (int i = tid; i < 64 * 64; i += 256) w1s[i] = W1[i];
    if (tid < 64) b1s[tid] = b1[tid];
    __syncthreads();

    long n = (long)blockIdx.x * 256 + tid;
    bool valid = n < n_nodes;
    long nc = valid ? n : (n_nodes - 1);
    const float4 *xr = (const float4 *)(x + nc * DIM);
#pragma unroll
    for (int q = 0; q < 16; q++) {
        float4 v = xr[q];
        S[(4 * q + 0) * 256 + tid] = v.x; S[(4 * q + 1) * 256 + tid] = v.y;
        S[(4 * q + 2) * 256 + tid] = v.z; S[(4 * q + 3) * 256 + tid] = v.w;
    }
    ull acc[32];
#pragma unroll
    for (int q = 0; q < 32; q++) acc[q] = pack2(b1s[2 * q], b1s[2 * q + 1]);
    const ulonglong2 *wp = (const ulonglong2 *)w1s;
#pragma unroll 2
    for (int k = 0; k < 64; k++) {
        float av = S[k * 256 + tid];
        ull aa = pack2(av, av);
#pragma unroll
        for (int q = 0; q < 16; q++) {
            ulonglong2 w = wp[k * 16 + q];
            fma2(acc[2 * q], aa, w.x);
            fma2(acc[2 * q + 1], aa, w.y);
        }
    }
    if (valid) {
        float4 *o = (float4 *)(g_xw + n * DIM);
#pragma unroll
        for (int q = 0; q < 16; q++) {
            float a, b, c, d;
            unpack2(a, b, acc[2 * q]); unpack2(c, d, acc[2 * q + 1]);
            o[q] = make_float4(a, b, c, d);
        }
    }
}

// ---------------------------------------------------------------------------
// Kernel 2: single-pass fp16 mma.sync edge MLP + scatter, pipelined.
// 64 HMMA + 40 LDSM per 16-edge tile. cp.async xw prefetch; ea register
// double-buffering; edge_index prefetched one tile ahead.
// SMEM per CTA:
//   [0,8K)   W1H ([n][k] fp16 rows of 128B, swizzled)  [8K,16K) W2H
//   16K + wid*6528 : AF(2K) XW(16 x 272B = 4352)
//   68608    : b2 (256B)
// ---------------------------------------------------------------------------
#define WBUF_STRIDE 6528
#define SM_B2 (16384 + 8 * WBUF_STRIDE)
#define SM_TOTAL (SM_B2 + 256)
#define XW_PITCH 272

struct Frag { uint32_t x, y, z, w; };

// D += A(fp16) @ W(fp16)^T, single pass.
__device__ __forceinline__ void gemm_1pass(uint32_t aF, uint32_t wB,
                                           float d[8][4], int lane) {
    uint32_t a_row = (lane & 7) + ((lane >> 3) & 1) * 8;
    uint32_t a_kq  = (lane >> 4) * 16;
    uint32_t b_row = (lane & 7) + ((lane >> 4) & 1) * 8;
    uint32_t b_kq  = ((lane >> 3) & 1) * 16;
#pragma unroll
    for (int ks = 0; ks < 4; ks++) {
        uint32_t aoff = swz(a_row * 128 + ks * 32 + a_kq);
        Frag af;
        ldsm4(af.x, af.y, af.z, af.w, aF + aoff);
#pragma unroll
        for (int p = 0; p < 4; p++) {
            uint32_t boff = swz((b_row + p * 16) * 128 + ks * 32 + b_kq);
            Frag bf;
            ldsm4(bf.x, bf.y, bf.z, bf.w, wB + boff);
            mma16816(d[2 * p],     af.x, af.y, af.z, af.w, bf.x, bf.y);
            mma16816(d[2 * p + 1], af.x, af.y, af.z, af.w, bf.z, bf.w);
        }
    }
}

__global__ __launch_bounds__(256, 2)
void edge_kernel(const float *__restrict__ edge_attr,
                 const float *__restrict__ W1,
                 const float *__restrict__ W2,
                 const float *__restrict__ b2,
                 const int *__restrict__ edge_index,
                 float *__restrict__ out_node,
                 float *__restrict__ out_edge,
                 int n_edges, int n_wtiles) {
    extern __shared__ char smc[];
    uint32_t sb = smem_u32(smc);
    int tid = threadIdx.x;
    int wid = tid >> 5, lane = tid & 31;

    // ---- stage fp16 weights ([n][k] rows of 128B, swizzled) ----
    for (int i = tid; i < 4096; i += 256) {
        int kk = i >> 6, n = i & 63;
        uint32_t off = swz((uint32_t)(n * 128 + kk * 2));
        *(uint16_t *)(smc + 0    + off) =
            __half_as_ushort(__float2half_rn(W1[(64 + kk) * 64 + n]));
        *(uint16_t *)(smc + 8192 + off) =
            __half_as_ushort(__float2half_rn(W2[kk * 64 + n]));
    }
    if (tid < 64) ((float *)(smc + SM_B2))[tid] = b2[tid];
    __syncthreads();

    const uint32_t W1H = sb, W2H = sb + 8192;
    char *wbuf = smc + 16384 + wid * WBUF_STRIDE;    // AF (2KB)
    char *xwbuf = wbuf + 2048;                       // 16 x 272B
    const uint32_t AF = sb + 16384 + wid * WBUF_STRIDE;
    const uint32_t XW = AF + 2048;

    int q = lane >> 2, cb = 2 * (lane & 3);          // D-fragment mapping
    int row2 = lane >> 1, hf = lane & 1;             // gather/store mapping
    int nwarps = gridDim.x * 8;
    int wgid = blockIdx.x * 8 + wid;

    // preload first tile's ea + edge indices
    float4 ea[8];
    int idxv = 0;
    if (wgid < n_wtiles) {
        int base = wgid * 16;
#pragma unroll
        for (int j = 0; j < 8; j++) {
            int idx = j * 32 + lane;
            int e = base + (idx >> 4); if (e >= n_edges) e = n_edges - 1;
            ea[j] = *(const float4 *)(edge_attr + (long)e * 64 + (idx & 15) * 4);
        }
        int pos = base + (lane & 15);
        if (pos >= n_edges) pos = n_edges - 1;
        idxv = edge_index[(lane < 16 ? 0 : n_edges) + pos];
    }

    for (int wt = wgid; wt < n_wtiles; wt += nwarps) {
        int base_e = wt * 16;

        // ---- src/dst from prefetched index register ----
        int srcr = __shfl_sync(0xffffffffu, idxv, row2);
        int dstr = __shfl_sync(0xffffffffu, idxv, 16 + row2);

        // ---- cp.async prefetch of xw[src] rows (4KB gather) ----
        {
            const float *g = g_xw + (long)srcr * 64 + hf * 32;
            uint32_t d = XW + row2 * XW_PITCH + hf * 128;
#pragma unroll
            for (int i = 0; i < 8; i++) cp16(d + i * 16, g + i * 4);
            asm volatile("cp.async.commit_group;" ::: "memory");
        }

        // ---- stage ea registers -> fp16 A tile ----
#pragma unroll
        for (int j = 0; j < 8; j++) {
            int idx = j * 32 + lane;
            int m = idx >> 4, c = idx & 15;
            uint32_t h01 = pack_h2(ea[j].x, ea[j].y);
            uint32_t h23 = pack_h2(ea[j].z, ea[j].w);
            uint32_t off = swz((uint32_t)(m * 128 + c * 8));
            *(uint2 *)(wbuf + off) = make_uint2(h01, h23);
        }
        __syncwarp();

        // ---- issue next tile's ea + index loads (consumed next iter) ----
        int wtn = wt + nwarps;
        if (wtn < n_wtiles) {
            int base = wtn * 16;
#pragma unroll
            for (int j = 0; j < 8; j++) {
                int idx = j * 32 + lane;
                int e = base + (idx >> 4); if (e >= n_edges) e = n_edges - 1;
                ea[j] = *(const float4 *)(edge_attr + (long)e * 64 + (idx & 15) * 4);
            }
            int pos = base + (lane & 15);
            if (pos >= n_edges) pos = n_edges - 1;
            idxv = edge_index[(lane < 16 ? 0 : n_edges) + pos];
        }

        // ---- GEMM1: D1 = ea @ W1b ----
        float d1[8][4];
#pragma unroll
        for (int j = 0; j < 8; j++)
            d1[j][0] = d1[j][1] = d1[j][2] = d1[j][3] = 0.f;
        gemm_1pass(AF, W1H, d1, lane);

        // ---- epilogue 1: h = relu(D1 + xw) from prefetched smem ----
        asm volatile("cp.async.wait_group 0;" ::: "memory");
        __syncwarp();
        const float *xw0 = (const float *)(xwbuf + q * XW_PITCH);
        const float *xw1 = (const float *)(xwbuf + (q + 8) * XW_PITCH);
#pragma unroll
        for (int j = 0; j < 8; j++) {
            float2 x0 = *(const float2 *)(xw0 + j * 8 + cb);
            float2 x1 = *(const float2 *)(xw1 + j * 8 + cb);
            float h00 = fmaxf(d1[j][0] + x0.x, 0.f);
            float h01 = fmaxf(d1[j][1] + x0.y, 0.f);
            float h10 = fmaxf(d1[j][2] + x1.x, 0.f);
            float h11 = fmaxf(d1[j][3] + x1.y, 0.f);
            uint32_t off0 = swz((uint32_t)(q * 128 + (j * 8 + cb) * 2));
            uint32_t off1 = swz((uint32_t)((q + 8) * 128 + (j * 8 + cb) * 2));
            *(uint32_t *)(wbuf + off0) = pack_h2(h00, h01);
            *(uint32_t *)(wbuf + off1) = pack_h2(h10, h11);
        }
        __syncwarp();

        // ---- GEMM2: D2 = h @ W2 ----
        float d2[8][4];
#pragma unroll
        for (int j = 0; j < 8; j++)
            d2[j][0] = d2[j][1] = d2[j][2] = d2[j][3] = 0.f;
        gemm_1pass(AF, W2H, d2, lane);

        // ---- epilogue 2: transpose via xw buffer, + b2, store+scatter ----
        float *sc = (float *)xwbuf;                  // rows of 68 floats
#pragma unroll
        for (int j = 0; j < 8; j++) {
            *(float2 *)(sc + q * 68 + j * 8 + cb) =
                make_float2(d2[j][0], d2[j][1]);
            *(float2 *)(sc + (q + 8) * 68 + j * 8 + cb) =
                make_float2(d2[j][2], d2[j][3]);
        }
        __syncwarp();
        {
            int er = base_e + row2;
            if (er < n_edges) {
                const float4 *s4 = (const float4 *)(sc + row2 * 68 + hf * 32);
                const float4 *b2v = (const float4 *)(smc + SM_B2 + hf * 128);
                float4 *oe = (float4 *)(out_edge + (long)er * 64 + hf * 32);
                float *on = out_node + (long)dstr * 64 + hf * 32;
#pragma unroll
                for (int t = 0; t < 8; t++) {
                    float4 v = s4[t], b = b2v[t];
                    v.x += b.x; v.y += b.y; v.z += b.z; v.w += b.w;
                    oe[t] = v;
                    red_v4(on + 4 * t, v);
                }
                if (hf == 0)
                    asm volatile("red.global.add.f32 [%0], %1;"
                                 :: "l"(g_cnt + dstr), "f"(1.0f) : "memory");
            }
        }
        __syncwarp();
    }
}

// ---------------------------------------------------------------------------
// Kernel 3: node_new = node_sum / max(cnt, 1)
// ---------------------------------------------------------------------------
__global__ void finalize_kernel(float4 *out_node4, int n_nodes) {
    int i = blockIdx.x * blockDim.x + threadIdx.x;
    int total4 = n_nodes * (DIM / 4);
    if (i >= total4) return;
    int n = i >> 4;
    float inv = 1.0f / fmaxf(g_cnt[n], 1.0f);
    float4 v = out_node4[i];
    v.x *= inv; v.y *= inv; v.z *= inv; v.w *= inv;
    out_node4[i] = v;
}

// ---------------------------------------------------------------------------
extern "C" void kernel_launch(void* const* d_in, const int* in_sizes, int n_in,
                              void* d_out, int out_size) {
    const float *x    = (const float *)d_in[0];
    const float *ea   = (const float *)d_in[1];
    const float *W1   = (const float *)d_in[2];
    const float *b1   = (const float *)d_in[3];
    const float *W2   = (const float *)d_in[4];
    const float *b2   = (const float *)d_in[5];
    const int   *eidx = (const int *)d_in[6];

    int n_nodes = in_sizes[0] / DIM;
    int n_edges = in_sizes[1] / DIM;

    float *out_node = (float *)d_out;
    float *out_edge = out_node + (size_t)n_nodes * DIM;

    const int smem_pre = (64 * 256 + 64 * 64 + 64) * 4;
    cudaFuncSetAttribute(node_pre_kernel,
                         cudaFuncAttributeMaxDynamicSharedMemorySize, smem_pre);
    cudaFuncSetAttribute(edge_kernel,
                         cudaFuncAttributeMaxDynamicSharedMemorySize, SM_TOTAL);

    int z_grid = (n_nodes * (DIM / 4) + 255) / 256;
    zero_kernel<<<z_grid, 256>>>((float4 *)out_node, n_nodes);

    int pre_grid = (n_nodes + 255) / 256;
    node_pre_kernel<<<pre_grid, 256, smem_pre>>>(x, W1, b1, n_nodes);

    int n_wtiles = (n_edges + 15) / 16;
    int grid = 296;
    int max_grid = (n_wtiles + 7) / 8;
    if (grid > max_grid) grid = max_grid;
    edge_kernel<<<grid, 256, SM_TOTAL>>>(ea, W1, W2, b2, eidx,
                                         out_node, out_edge, n_edges, n_wtiles);

    finalize_kernel<<<z_grid, 256>>>((float4 *)out_node, n_nodes);
}